// round 3
// baseline (speedup 1.0000x reference)
#include <cuda_runtime.h>
#include <cstdint>

#define NN 50000
#define EE 800000
#define IN_C 128
#define HID 256
#define OUT_C 15

// ---------------- scratch (static device globals; no allocation) ----------------
__device__ int   g_rowptr[NN + 1];
__device__ int   g_fill[NN];          // per-node count, then fill cursor
__device__ int   g_esrc[EE];
__device__ float g_inv[NN];
__device__ int   g_is64;              // edge_index dtype flag (1 = int64, 0 = int32)
__device__ float g_mean[(size_t)NN * HID];
__device__ float g_bufA[(size_t)NN * HID];
__device__ float g_bufB[(size_t)NN * HID];

template <int ID>
__device__ __forceinline__ float* sbuf() {
    if (ID == 0) return g_mean;
    if (ID == 1) return g_bufA;
    return g_bufB;
}

// read edge index value at flat position p, honoring detected dtype
__device__ __forceinline__ int edge_at(const void* eiv, int p) {
    if (g_is64) return (int)((const long long*)eiv)[p];
    return ((const int*)eiv)[p];
}

// ---------------- dtype detection ----------------
__global__ void k_detect(const void* eiv) {
    if (threadIdx.x == 0 && blockIdx.x == 0) {
        const long long* e64 = (const long long*)eiv;
        int ok64 = 1;
        for (int i = 0; i < 64; i++) {
            long long v = e64[i];
            if (v < 0 || v >= NN) { ok64 = 0; break; }
        }
        g_is64 = ok64;
    }
}

// ---------------- CSR build ----------------
__global__ void k_zero_counts() {
    int i = blockIdx.x * blockDim.x + threadIdx.x;
    if (i < NN) g_fill[i] = 0;
}

__global__ void k_count(const void* __restrict__ eiv) {
    int e = blockIdx.x * blockDim.x + threadIdx.x;
    if (e < EE) {
        int dst = edge_at(eiv, EE + e);
        if ((unsigned)dst < NN) atomicAdd(&g_fill[dst], 1);
    }
}

// single-block exclusive scan over counts -> rowptr; also inv counts; resets fill.
__global__ void k_scan() {
    __shared__ int ssum[1024];
    const int t = threadIdx.x;
    const int CHUNK = (NN + 1023) / 1024;   // 49
    int lo = t * CHUNK;
    int hi = lo + CHUNK; if (hi > NN) hi = NN;
    if (lo > NN) lo = NN;
    int s = 0;
    for (int i = lo; i < hi; i++) s += g_fill[i];
    ssum[t] = s;
    __syncthreads();
    for (int off = 1; off < 1024; off <<= 1) {
        int v = (t >= off) ? ssum[t - off] : 0;
        __syncthreads();
        ssum[t] += v;
        __syncthreads();
    }
    int base = (t == 0) ? 0 : ssum[t - 1];
    for (int i = lo; i < hi; i++) {
        int c = g_fill[i];
        g_rowptr[i] = base;
        g_inv[i] = 1.0f / (float)(c > 1 ? c : 1);
        g_fill[i] = 0;
        base += c;
    }
    if (t == 1023) g_rowptr[NN] = ssum[1023];
}

__global__ void k_fill(const void* __restrict__ eiv) {
    int e = blockIdx.x * blockDim.x + threadIdx.x;
    if (e < EE) {
        int src = edge_at(eiv, e);
        int dst = edge_at(eiv, EE + e);
        if ((unsigned)dst < NN && (unsigned)src < NN) {
            int pos = atomicAdd(&g_fill[dst], 1);
            g_esrc[g_rowptr[dst] + pos] = src;
        }
    }
}

// ---------------- aggregation: one warp per destination node ----------------
template <int D, int SRC, int DST>
__global__ __launch_bounds__(256) void k_aggregate(const float* __restrict__ xin) {
    const float* __restrict__ x = (SRC < 0) ? xin : sbuf<SRC>();
    float* __restrict__ out = sbuf<DST>();

    int node = blockIdx.x * 8 + (threadIdx.x >> 5);
    if (node >= NN) return;
    int lane = threadIdx.x & 31;
    int beg = g_rowptr[node], end = g_rowptr[node + 1];

    float4 a0 = make_float4(0.f, 0.f, 0.f, 0.f);
    float4 a1 = make_float4(0.f, 0.f, 0.f, 0.f);

    int e = beg;
    for (; e + 1 < end; e += 2) {
        int s0 = g_esrc[e];
        int s1 = g_esrc[e + 1];
        const float4* r0 = (const float4*)(x + (size_t)s0 * D);
        const float4* r1 = (const float4*)(x + (size_t)s1 * D);
        float4 v0 = __ldg(r0 + lane);
        float4 v1 = __ldg(r1 + lane);
        a0.x += v0.x; a0.y += v0.y; a0.z += v0.z; a0.w += v0.w;
        a0.x += v1.x; a0.y += v1.y; a0.z += v1.z; a0.w += v1.w;
        if (D == 256) {
            float4 w0 = __ldg(r0 + 32 + lane);
            float4 w1 = __ldg(r1 + 32 + lane);
            a1.x += w0.x; a1.y += w0.y; a1.z += w0.z; a1.w += w0.w;
            a1.x += w1.x; a1.y += w1.y; a1.z += w1.z; a1.w += w1.w;
        }
    }
    if (e < end) {
        int s0 = g_esrc[e];
        const float4* r0 = (const float4*)(x + (size_t)s0 * D);
        float4 v0 = __ldg(r0 + lane);
        a0.x += v0.x; a0.y += v0.y; a0.z += v0.z; a0.w += v0.w;
        if (D == 256) {
            float4 w0 = __ldg(r0 + 32 + lane);
            a1.x += w0.x; a1.y += w0.y; a1.z += w0.z; a1.w += w0.w;
        }
    }
    float inv = g_inv[node];
    float4* o = (float4*)(out + (size_t)node * D);
    o[lane] = make_float4(a0.x * inv, a0.y * inv, a0.z * inv, a0.w * inv);
    if (D == 256)
        o[32 + lane] = make_float4(a1.x * inv, a1.y * inv, a1.z * inv, a1.w * inv);
}

// ---------------- fused SAGE GEMM: C = relu(mean@Wl + h@Wr + b) ----------------
template <int D, int AH, int CID>
__global__ __launch_bounds__(256) void k_sage_gemm(const float* __restrict__ xin,
                                                   const float* __restrict__ Wl,
                                                   const float* __restrict__ Wr,
                                                   const float* __restrict__ bias) {
    const float* __restrict__ Am = g_mean;
    const float* __restrict__ Ah = (AH < 0) ? xin : sbuf<AH>();
    float* __restrict__ C = sbuf<CID>();

    constexpr int BM = 128, BN = 128, BK = 8;
    __shared__ float As[BK][BM];
    __shared__ float Bs[BK][BN];

    const int row0 = blockIdx.x * BM;
    const int col0 = blockIdx.y * BN;
    const int tid = threadIdx.x;
    const int tm = tid >> 4;        // 0..15
    const int tn = tid & 15;        // 0..15

    const int aRow = tid >> 1;            // 0..127
    const int aCol = (tid & 1) * 4;       // 0 or 4
    const int bRow = tid >> 5;            // 0..7
    const int bCol = (tid & 31) * 4;      // 0..124

    float acc[8][8];
#pragma unroll
    for (int i = 0; i < 8; i++)
#pragma unroll
        for (int j = 0; j < 8; j++) acc[i][j] = 0.f;

#pragma unroll
    for (int pass = 0; pass < 2; pass++) {
        const float* A = pass ? Ah : Am;
        const float* W = pass ? Wr : Wl;
        for (int k0 = 0; k0 < D; k0 += BK) {
            int gr = row0 + aRow;
            float4 av = (gr < NN)
                ? *(const float4*)(A + (size_t)gr * D + k0 + aCol)
                : make_float4(0.f, 0.f, 0.f, 0.f);
            As[aCol + 0][aRow] = av.x;
            As[aCol + 1][aRow] = av.y;
            As[aCol + 2][aRow] = av.z;
            As[aCol + 3][aRow] = av.w;

            float4 bv = *(const float4*)(W + (size_t)(k0 + bRow) * HID + col0 + bCol);
            *(float4*)&Bs[bRow][bCol] = bv;
            __syncthreads();

#pragma unroll
            for (int k = 0; k < BK; k++) {
                float4 a0 = *(const float4*)&As[k][tm * 8];
                float4 a1 = *(const float4*)&As[k][tm * 8 + 4];
                float4 b0 = *(const float4*)&Bs[k][tn * 8];
                float4 b1 = *(const float4*)&Bs[k][tn * 8 + 4];
                float ra[8] = {a0.x, a0.y, a0.z, a0.w, a1.x, a1.y, a1.z, a1.w};
                float rb[8] = {b0.x, b0.y, b0.z, b0.w, b1.x, b1.y, b1.z, b1.w};
#pragma unroll
                for (int i = 0; i < 8; i++)
#pragma unroll
                    for (int j = 0; j < 8; j++) acc[i][j] += ra[i] * rb[j];
            }
            __syncthreads();
        }
    }

#pragma unroll
    for (int i = 0; i < 8; i++) {
        int gr = row0 + tm * 8 + i;
        if (gr >= NN) continue;
#pragma unroll
        for (int j = 0; j < 8; j += 4) {
            int gc = col0 + tn * 8 + j;
            float4 v;
            v.x = fmaxf(acc[i][j + 0] + __ldg(bias + gc + 0), 0.f);
            v.y = fmaxf(acc[i][j + 1] + __ldg(bias + gc + 1), 0.f);
            v.z = fmaxf(acc[i][j + 2] + __ldg(bias + gc + 2), 0.f);
            v.w = fmaxf(acc[i][j + 3] + __ldg(bias + gc + 3), 0.f);
            *(float4*)(C + (size_t)gr * HID + gc) = v;
        }
    }
}

// ---------------- output layer: out = g_bufA @ Wo + bo ----------------
__global__ __launch_bounds__(256) void k_out_gemm(const float* __restrict__ Wo,
                                                  const float* __restrict__ bo,
                                                  float* __restrict__ out) {
    const float* __restrict__ H = g_bufA;
    __shared__ float sW[HID * OUT_C];     // 15 KB
    __shared__ float sH[16][HID];         // 16 KB
    const int tid = threadIdx.x;
    for (int i = tid; i < HID * OUT_C; i += 256) sW[i] = Wo[i];

    const int row0 = blockIdx.x * 16;
    for (int i = tid; i < 16 * (HID / 4); i += 256) {
        int r = i >> 6;               // 0..15
        int c4 = (i & 63) * 4;        // 0..252
        int gr = row0 + r;
        float4 v = (gr < NN) ? *(const float4*)(H + (size_t)gr * HID + c4)
                             : make_float4(0.f, 0.f, 0.f, 0.f);
        *(float4*)&sH[r][c4] = v;
    }
    __syncthreads();

    int r = tid >> 4;       // 0..15
    int c = tid & 15;       // 0..15
    if (c < OUT_C) {
        float acc = 0.f;
#pragma unroll 8
        for (int k = 0; k < HID; k++) acc += sH[r][k] * sW[k * OUT_C + c];
        int gr = row0 + r;
        if (gr < NN) out[(size_t)gr * OUT_C + c] = acc + bo[c];
    }
}

// ---------------- launch ----------------
extern "C" void kernel_launch(void* const* d_in, const int* in_sizes, int n_in,
                              void* d_out, int out_size) {
    const float* x   = (const float*)d_in[0];
    const void*  ei  = d_in[1];
    const float* Wl1 = (const float*)d_in[2];
    const float* bl1 = (const float*)d_in[3];
    const float* Wr1 = (const float*)d_in[4];
    const float* Wl2 = (const float*)d_in[5];
    const float* bl2 = (const float*)d_in[6];
    const float* Wr2 = (const float*)d_in[7];
    const float* Wl3 = (const float*)d_in[8];
    const float* bl3 = (const float*)d_in[9];
    const float* Wr3 = (const float*)d_in[10];
    const float* Wo  = (const float*)d_in[11];
    const float* bo  = (const float*)d_in[12];
    float* out = (float*)d_out;

    // dtype detect + CSR build (counts -> scan -> fill)
    k_detect<<<1, 32>>>(ei);
    k_zero_counts<<<(NN + 255) / 256, 256>>>();
    k_count<<<(EE + 255) / 256, 256>>>(ei);
    k_scan<<<1, 1024>>>();
    k_fill<<<(EE + 255) / 256, 256>>>(ei);

    dim3 ggrid((NN + 127) / 128, HID / 128);

    // layer 1: aggregate x (d=128) -> g_mean; gemm -> g_bufA
    k_aggregate<IN_C, -1, 0><<<(NN + 7) / 8, 256>>>(x);
    k_sage_gemm<IN_C, -1, 1><<<ggrid, 256>>>(x, Wl1, Wr1, bl1);

    // layer 2: aggregate g_bufA -> g_mean; gemm -> g_bufB
    k_aggregate<HID, 1, 0><<<(NN + 7) / 8, 256>>>(nullptr);
    k_sage_gemm<HID, 1, 2><<<ggrid, 256>>>(nullptr, Wl2, Wr2, bl2);

    // layer 3: aggregate g_bufB -> g_mean; gemm -> g_bufA
    k_aggregate<HID, 2, 0><<<(NN + 7) / 8, 256>>>(nullptr);
    k_sage_gemm<HID, 2, 1><<<ggrid, 256>>>(nullptr, Wl3, Wr3, bl3);

    // output projection from g_bufA
    k_out_gemm<<<(NN + 15) / 16, 256>>>(Wo, bo, out);
}

// round 4
// speedup vs baseline: 1.8777x; 1.8777x over previous
#include <cuda_runtime.h>
#include <cstdint>

#define NN 50000
#define EE 800000
#define IN_C 128
#define HID 256
#define OUT_C 15
#define SCAN_BLKS ((NN + 255) / 256)   // 196

// ---------------- scratch (static device globals; no allocation) ----------------
__device__ int   g_rowptr[NN + 1];
__device__ int   g_fill[NN];
__device__ int   g_esrc[EE];
__device__ float g_inv[NN];
__device__ int   g_is64;
__device__ int   g_blksum[256];
__device__ float g_mean[(size_t)NN * HID];
__device__ float g_bufA[(size_t)NN * HID];
__device__ float g_bufB[(size_t)NN * HID];

template <int ID>
__device__ __forceinline__ float* sbuf() {
    if (ID == 0) return g_mean;
    if (ID == 1) return g_bufA;
    return g_bufB;
}

__device__ __forceinline__ int edge_at(const void* eiv, int p) {
    if (g_is64) return (int)((const long long*)eiv)[p];
    return ((const int*)eiv)[p];
}

__device__ __forceinline__ float to_tf32(float x) {
    uint32_t u;
    asm("cvt.rna.tf32.f32 %0, %1;" : "=r"(u) : "f"(x));
    return __uint_as_float(u);
}

__device__ __forceinline__ void mma_tf32(float* d, const float* a, const float* b) {
    asm volatile(
        "mma.sync.aligned.m16n8k8.row.col.f32.tf32.tf32.f32 "
        "{%0,%1,%2,%3}, {%4,%5,%6,%7}, {%8,%9}, {%0,%1,%2,%3};\n"
        : "+f"(d[0]), "+f"(d[1]), "+f"(d[2]), "+f"(d[3])
        : "r"(__float_as_uint(a[0])), "r"(__float_as_uint(a[1])),
          "r"(__float_as_uint(a[2])), "r"(__float_as_uint(a[3])),
          "r"(__float_as_uint(b[0])), "r"(__float_as_uint(b[1])));
}

// ---------------- dtype detection ----------------
__global__ void k_detect(const void* eiv) {
    if (threadIdx.x == 0 && blockIdx.x == 0) {
        const long long* e64 = (const long long*)eiv;
        int ok64 = 1;
        for (int i = 0; i < 64; i++) {
            long long v = e64[i];
            if (v < 0 || v >= NN) { ok64 = 0; break; }
        }
        g_is64 = ok64;
    }
}

// ---------------- CSR build ----------------
__global__ void k_zero_counts() {
    int i = blockIdx.x * blockDim.x + threadIdx.x;
    if (i < NN) g_fill[i] = 0;
}

__global__ void k_count(const void* __restrict__ eiv) {
    int e = blockIdx.x * blockDim.x + threadIdx.x;
    if (e < EE) {
        int dst = edge_at(eiv, EE + e);
        if ((unsigned)dst < NN) atomicAdd(&g_fill[dst], 1);
    }
}

// parallel scan, stage 1: per-block exclusive scan of counts; emit block sums
__global__ __launch_bounds__(256) void k_local_scan() {
    __shared__ int sh[256];
    int t = threadIdx.x;
    int i = blockIdx.x * 256 + t;
    int c = (i < NN) ? g_fill[i] : 0;
    sh[t] = c;
    __syncthreads();
#pragma unroll
    for (int off = 1; off < 256; off <<= 1) {
        int v = (t >= off) ? sh[t - off] : 0;
        __syncthreads();
        sh[t] += v;
        __syncthreads();
    }
    if (i < NN) {
        g_rowptr[i] = sh[t] - c;                 // exclusive within block
        g_inv[i] = 1.0f / (float)(c > 1 ? c : 1);
        g_fill[i] = 0;                           // reset for fill pass
    }
    if (t == 255) g_blksum[blockIdx.x] = sh[255];
}

// stage 2: exclusive scan of block sums (single block)
__global__ __launch_bounds__(256) void k_blk_scan() {
    __shared__ int sh[256];
    int t = threadIdx.x;
    int v = (t < SCAN_BLKS) ? g_blksum[t] : 0;
    sh[t] = v;
    __syncthreads();
#pragma unroll
    for (int off = 1; off < 256; off <<= 1) {
        int u = (t >= off) ? sh[t - off] : 0;
        __syncthreads();
        sh[t] += u;
        __syncthreads();
    }
    if (t < SCAN_BLKS) g_blksum[t] = sh[t] - v;  // exclusive
    if (t == 255) g_rowptr[NN] = sh[255];
}

// stage 3: add block offsets
__global__ __launch_bounds__(256) void k_add_off() {
    int i = blockIdx.x * 256 + threadIdx.x;
    if (i < NN) g_rowptr[i] += g_blksum[blockIdx.x];
}

__global__ void k_fill(const void* __restrict__ eiv) {
    int e = blockIdx.x * blockDim.x + threadIdx.x;
    if (e < EE) {
        int src = edge_at(eiv, e);
        int dst = edge_at(eiv, EE + e);
        if ((unsigned)dst < NN && (unsigned)src < NN) {
            int pos = atomicAdd(&g_fill[dst], 1);
            g_esrc[g_rowptr[dst] + pos] = src;
        }
    }
}

// ---------------- aggregation: one warp per destination node ----------------
template <int D, int SRC, int DST>
__global__ __launch_bounds__(256) void k_aggregate(const float* __restrict__ xin) {
    const float* __restrict__ x = (SRC < 0) ? xin : sbuf<SRC>();
    float* __restrict__ out = sbuf<DST>();

    int node = blockIdx.x * 8 + (threadIdx.x >> 5);
    if (node >= NN) return;
    int lane = threadIdx.x & 31;
    int beg = g_rowptr[node], end = g_rowptr[node + 1];

    float4 a0 = make_float4(0.f, 0.f, 0.f, 0.f);
    float4 a1 = make_float4(0.f, 0.f, 0.f, 0.f);

    int e = beg;
    for (; e + 1 < end; e += 2) {
        int s0 = g_esrc[e];
        int s1 = g_esrc[e + 1];
        const float4* r0 = (const float4*)(x + (size_t)s0 * D);
        const float4* r1 = (const float4*)(x + (size_t)s1 * D);
        float4 v0 = __ldg(r0 + lane);
        float4 v1 = __ldg(r1 + lane);
        a0.x += v0.x; a0.y += v0.y; a0.z += v0.z; a0.w += v0.w;
        a0.x += v1.x; a0.y += v1.y; a0.z += v1.z; a0.w += v1.w;
        if (D == 256) {
            float4 w0 = __ldg(r0 + 32 + lane);
            float4 w1 = __ldg(r1 + 32 + lane);
            a1.x += w0.x; a1.y += w0.y; a1.z += w0.z; a1.w += w0.w;
            a1.x += w1.x; a1.y += w1.y; a1.z += w1.z; a1.w += w1.w;
        }
    }
    if (e < end) {
        int s0 = g_esrc[e];
        const float4* r0 = (const float4*)(x + (size_t)s0 * D);
        float4 v0 = __ldg(r0 + lane);
        a0.x += v0.x; a0.y += v0.y; a0.z += v0.z; a0.w += v0.w;
        if (D == 256) {
            float4 w0 = __ldg(r0 + 32 + lane);
            a1.x += w0.x; a1.y += w0.y; a1.z += w0.z; a1.w += w0.w;
        }
    }
    float inv = g_inv[node];
    float4* o = (float4*)(out + (size_t)node * D);
    o[lane] = make_float4(a0.x * inv, a0.y * inv, a0.z * inv, a0.w * inv);
    if (D == 256)
        o[32 + lane] = make_float4(a1.x * inv, a1.y * inv, a1.z * inv, a1.w * inv);
}

// ---------------- fused SAGE GEMM (tf32 tensor cores) ----------------
// C = relu(mean@Wl + h@Wr + bias);  mean = g_mean, h = xin or sbuf<AH>, C = sbuf<CID>
// BM=128, BN=128, BK=16; 8 warps, each computing a 32x64 warp tile via m16n8k8 atoms.
template <int D, int AH, int CID>
__global__ __launch_bounds__(256) void k_sage_mma(const float* __restrict__ xin,
                                                  const float* __restrict__ Wl,
                                                  const float* __restrict__ Wr,
                                                  const float* __restrict__ bias) {
    const float* __restrict__ Am = g_mean;
    const float* __restrict__ Ah = (AH < 0) ? xin : sbuf<AH>();
    float* __restrict__ C = sbuf<CID>();

    constexpr int BM = 128, BN = 128, BK = 16;
    constexpr int LDA = BM + 4;   // 132: fragment reads conflict-free
    constexpr int LDB = BN + 4;
    __shared__ float As[BK][LDA];
    __shared__ float Bs[BK][LDB];

    const int row0 = blockIdx.x * BM;
    const int col0 = blockIdx.y * BN;
    const int tid = threadIdx.x;
    const int warp = tid >> 5;
    const int lane = tid & 31;
    const int warpM = warp & 3;        // 4 warps over M (32 rows each)
    const int warpN = warp >> 2;       // 2 warps over N (64 cols each)
    const int g  = lane >> 2;          // groupID 0..7
    const int tg = lane & 3;           // thread-in-group 0..3

    // A loader: 2 iters, float4 at (row = (tid>>2)+it*64, col4 = (tid&3)*4)
    const int aRow = tid >> 2;         // 0..63
    const int aCol = (tid & 3) * 4;    // 0,4,8,12
    // B loader: 2 iters, float4 at (row = idx>>5, col4 = (idx&31)*4), idx = tid + it*256
    float acc[2][8][4];
#pragma unroll
    for (int i = 0; i < 2; i++)
#pragma unroll
        for (int j = 0; j < 8; j++)
#pragma unroll
            for (int r = 0; r < 4; r++) acc[i][j][r] = 0.f;

#pragma unroll
    for (int pass = 0; pass < 2; pass++) {
        const float* A = pass ? Ah : Am;
        const float* W = pass ? Wr : Wl;
        for (int k0 = 0; k0 < D; k0 += BK) {
            // ---- load A tile (rows guarded, tf32-rounded) ----
#pragma unroll
            for (int it = 0; it < 2; it++) {
                int r = aRow + it * 64;
                int gr = row0 + r;
                float4 av = (gr < NN)
                    ? *(const float4*)(A + (size_t)gr * D + k0 + aCol)
                    : make_float4(0.f, 0.f, 0.f, 0.f);
                As[aCol + 0][r] = to_tf32(av.x);
                As[aCol + 1][r] = to_tf32(av.y);
                As[aCol + 2][r] = to_tf32(av.z);
                As[aCol + 3][r] = to_tf32(av.w);
            }
            // ---- load B tile (tf32-rounded) ----
#pragma unroll
            for (int it = 0; it < 2; it++) {
                int idx = tid + it * 256;
                int r = idx >> 5;                 // 0..15
                int c4 = (idx & 31) * 4;          // 0..124
                float4 bv = *(const float4*)(W + (size_t)(k0 + r) * HID + col0 + c4);
                bv.x = to_tf32(bv.x); bv.y = to_tf32(bv.y);
                bv.z = to_tf32(bv.z); bv.w = to_tf32(bv.w);
                *(float4*)&Bs[r][c4] = bv;
            }
            __syncthreads();

#pragma unroll
            for (int ks = 0; ks < BK; ks += 8) {
                // fragments
                float af[2][4];
#pragma unroll
                for (int ma = 0; ma < 2; ma++) {
                    int m = warpM * 32 + ma * 16 + g;
                    af[ma][0] = As[ks + tg][m];
                    af[ma][1] = As[ks + tg][m + 8];
                    af[ma][2] = As[ks + tg + 4][m];
                    af[ma][3] = As[ks + tg + 4][m + 8];
                }
                float bf[8][2];
#pragma unroll
                for (int na = 0; na < 8; na++) {
                    int n = warpN * 64 + na * 8 + g;
                    bf[na][0] = Bs[ks + tg][n];
                    bf[na][1] = Bs[ks + tg + 4][n];
                }
#pragma unroll
                for (int ma = 0; ma < 2; ma++)
#pragma unroll
                    for (int na = 0; na < 8; na++)
                        mma_tf32(acc[ma][na], af[ma], bf[na]);
            }
            __syncthreads();
        }
    }

    // ---- epilogue: bias + relu ----
#pragma unroll
    for (int ma = 0; ma < 2; ma++) {
        int r0r = row0 + warpM * 32 + ma * 16 + g;
#pragma unroll
        for (int na = 0; na < 8; na++) {
            int c = col0 + warpN * 64 + na * 8 + tg * 2;
            float bx = __ldg(bias + c);
            float by = __ldg(bias + c + 1);
            if (r0r < NN) {
                float2 v;
                v.x = fmaxf(acc[ma][na][0] + bx, 0.f);
                v.y = fmaxf(acc[ma][na][1] + by, 0.f);
                *(float2*)(C + (size_t)r0r * HID + c) = v;
            }
            if (r0r + 8 < NN) {
                float2 v;
                v.x = fmaxf(acc[ma][na][2] + bx, 0.f);
                v.y = fmaxf(acc[ma][na][3] + by, 0.f);
                *(float2*)(C + (size_t)(r0r + 8) * HID + c) = v;
            }
        }
    }
}

// ---------------- output layer: out = g_bufA @ Wo + bo ----------------
__global__ __launch_bounds__(256) void k_out_gemm(const float* __restrict__ Wo,
                                                  const float* __restrict__ bo,
                                                  float* __restrict__ out) {
    const float* __restrict__ H = g_bufA;
    __shared__ float sW[HID * OUT_C];
    __shared__ float sH[16][HID];
    const int tid = threadIdx.x;
    for (int i = tid; i < HID * OUT_C; i += 256) sW[i] = Wo[i];

    const int row0 = blockIdx.x * 16;
    for (int i = tid; i < 16 * (HID / 4); i += 256) {
        int r = i >> 6;
        int c4 = (i & 63) * 4;
        int gr = row0 + r;
        float4 v = (gr < NN) ? *(const float4*)(H + (size_t)gr * HID + c4)
                             : make_float4(0.f, 0.f, 0.f, 0.f);
        *(float4*)&sH[r][c4] = v;
    }
    __syncthreads();

    int r = tid >> 4;
    int c = tid & 15;
    if (c < OUT_C) {
        float acc = 0.f;
#pragma unroll 8
        for (int k = 0; k < HID; k++) acc += sH[r][k] * sW[k * OUT_C + c];
        int gr = row0 + r;
        if (gr < NN) out[(size_t)gr * OUT_C + c] = acc + bo[c];
    }
}

// ---------------- launch ----------------
extern "C" void kernel_launch(void* const* d_in, const int* in_sizes, int n_in,
                              void* d_out, int out_size) {
    const float* x   = (const float*)d_in[0];
    const void*  ei  = d_in[1];
    const float* Wl1 = (const float*)d_in[2];
    const float* bl1 = (const float*)d_in[3];
    const float* Wr1 = (const float*)d_in[4];
    const float* Wl2 = (const float*)d_in[5];
    const float* bl2 = (const float*)d_in[6];
    const float* Wr2 = (const float*)d_in[7];
    const float* Wl3 = (const float*)d_in[8];
    const float* bl3 = (const float*)d_in[9];
    const float* Wr3 = (const float*)d_in[10];
    const float* Wo  = (const float*)d_in[11];
    const float* bo  = (const float*)d_in[12];
    float* out = (float*)d_out;

    // dtype detect + CSR build (counts -> parallel scan -> fill)
    k_detect<<<1, 32>>>(ei);
    k_zero_counts<<<(NN + 255) / 256, 256>>>();
    k_count<<<(EE + 255) / 256, 256>>>(ei);
    k_local_scan<<<SCAN_BLKS, 256>>>();
    k_blk_scan<<<1, 256>>>();
    k_add_off<<<SCAN_BLKS, 256>>>();
    k_fill<<<(EE + 255) / 256, 256>>>(ei);

    dim3 ggrid((NN + 127) / 128, HID / 128);

    // layer 1
    k_aggregate<IN_C, -1, 0><<<(NN + 7) / 8, 256>>>(x);
    k_sage_mma<IN_C, -1, 1><<<ggrid, 256>>>(x, Wl1, Wr1, bl1);

    // layer 2
    k_aggregate<HID, 1, 0><<<(NN + 7) / 8, 256>>>(nullptr);
    k_sage_mma<HID, 1, 2><<<ggrid, 256>>>(nullptr, Wl2, Wr2, bl2);

    // layer 3
    k_aggregate<HID, 2, 0><<<(NN + 7) / 8, 256>>>(nullptr);
    k_sage_mma<HID, 2, 1><<<ggrid, 256>>>(nullptr, Wl3, Wr3, bl3);

    // output projection
    k_out_gemm<<<(NN + 15) / 16, 256>>>(Wo, bo, out);
}